// round 2
// baseline (speedup 1.0000x reference)
#include <cuda_runtime.h>
#include <math.h>

// Problem constants (fixed dataset shapes)
#define NN 100000
#define NDIM 64
#define HDIM 128

// ---------------- scratch (__device__ globals; no allocation allowed) ----------------
__device__ float g_AB[NN * 256];      // per-node [A+b1 (128) | B (128)]
__device__ float g_Hagg[NN * 128];    // scatter-add of relu(hidden)
__device__ float g_degf[NN];          // in-degree (float)
__device__ float g_aggr[NN * 64];     // aggregated messages after W2
__device__ float g_gi[NN * 192];      // GRU input gates
__device__ float g_gh[NN * 192];      // GRU hidden gates
// repacked weights
__device__ float g_Wpre[64 * 256];    // [k][j] : j<128 -> W1a^T, else W1b^T
__device__ float g_b1ext[256];        // [b1 | 0]
__device__ float g_w1e[128];          // W1[:,128]
__device__ float g_W2t[128 * 64];     // W2 transposed [k][j]
__device__ float g_Wiht[64 * 192];    // W_ih transposed
__device__ float g_Whht[64 * 192];    // W_hh transposed

// ---------------- weight repack (runs every call; tiny) ----------------
__global__ void prep_kernel(const float* __restrict__ W1, const float* __restrict__ b1,
                            const float* __restrict__ W2,
                            const float* __restrict__ Wih, const float* __restrict__ Whh) {
    int t = blockIdx.x * blockDim.x + threadIdx.x;
    int stride = gridDim.x * blockDim.x;
    for (int i = t; i < 64 * 256; i += stride) {
        int k = i >> 8, j = i & 255;
        g_Wpre[i] = (j < 128) ? W1[j * 129 + k] : W1[(j - 128) * 129 + 64 + k];
    }
    for (int j = t; j < 256; j += stride) g_b1ext[j] = (j < 128) ? b1[j] : 0.f;
    for (int j = t; j < 128; j += stride) g_w1e[j] = W1[j * 129 + 128];
    for (int i = t; i < 128 * 64; i += stride) {
        int k = i >> 6, j = i & 63;
        g_W2t[i] = W2[j * 128 + k];
    }
    for (int i = t; i < 64 * 192; i += stride) {
        int k = i / 192, j = i % 192;
        g_Wiht[i] = Wih[j * 64 + k];
        g_Whht[i] = Whh[j * 64 + k];
    }
}

// ---------------- zero scratch accumulators (needed every graph replay) ----------------
__global__ void zero_kernel() {
    int t = blockIdx.x * blockDim.x + threadIdx.x;
    int stride = gridDim.x * blockDim.x;
    float4* H4 = reinterpret_cast<float4*>(g_Hagg);
    const float4 z = make_float4(0.f, 0.f, 0.f, 0.f);
    for (int i = t; i < NN * 128 / 4; i += stride) H4[i] = z;
    for (int i = t; i < NN; i += stride) g_degf[i] = 0.f;
}

// ---------------- generic tiled GEMM: C[M,NT] = A[M,KK] @ W[KK,NT] + bias ----------------
// EPI==0: + bias[j].  EPI==1: + rowscale[m]*bias[j].
template <int MT, int NT, int KK, int TM, int TN, int EPI>
__launch_bounds__(256, 2)
__global__ void gemm_k(const float* __restrict__ A, const float* __restrict__ W,
                       const float* __restrict__ bias, const float* __restrict__ rowscale,
                       float* __restrict__ C, int M) {
    constexpr int TCOLS = NT / TN;
    constexpr int TROWS = MT / TM;
    static_assert(TCOLS * TROWS == 256, "bad tiling");
    extern __shared__ float smem[];
    float* As = smem;             // MT x KK (row-major, contiguous tile of A)
    float* Ws = smem + MT * KK;   // KK x NT

    const int tid = threadIdx.x;
    const int m0 = blockIdx.x * MT;

    {   // cooperative loads (A tile is contiguous in gmem since KK == full K)
        const float4* Ag = reinterpret_cast<const float4*>(A) + (size_t)m0 * (KK / 4);
        float4* As4 = reinterpret_cast<float4*>(As);
        int rows = M - m0; if (rows > MT) rows = MT;
        const int lim = rows * (KK / 4);
        #pragma unroll 4
        for (int i = tid; i < MT * KK / 4; i += 256)
            As4[i] = (i < lim) ? Ag[i] : make_float4(0.f, 0.f, 0.f, 0.f);
        const float4* Wg = reinterpret_cast<const float4*>(W);
        float4* Ws4 = reinterpret_cast<float4*>(Ws);
        #pragma unroll 4
        for (int i = tid; i < KK * NT / 4; i += 256) Ws4[i] = Wg[i];
    }
    __syncthreads();

    const int tcol = tid % TCOLS;
    const int trow = tid / TCOLS;
    float acc[TM][TN];
    #pragma unroll
    for (int r = 0; r < TM; ++r)
        #pragma unroll
        for (int c = 0; c < TN; ++c) acc[r][c] = 0.f;

    const float* Abase = As + (trow * TM) * KK;
    const float* Wbase = Ws + tcol * TN;

    #pragma unroll 2
    for (int k4 = 0; k4 < KK; k4 += 4) {
        float4 a4[TM];
        #pragma unroll
        for (int r = 0; r < TM; ++r)
            a4[r] = *reinterpret_cast<const float4*>(Abase + r * KK + k4);
        #pragma unroll
        for (int kk = 0; kk < 4; ++kk) {
            float w[TN];
            const float* wrow = Wbase + (k4 + kk) * NT;
            #pragma unroll
            for (int c = 0; c < TN; ++c) w[c] = wrow[c];
            #pragma unroll
            for (int r = 0; r < TM; ++r) {
                const float av = (kk == 0) ? a4[r].x : (kk == 1) ? a4[r].y
                               : (kk == 2) ? a4[r].z : a4[r].w;
                #pragma unroll
                for (int c = 0; c < TN; ++c)
                    acc[r][c] = fmaf(av, w[c], acc[r][c]);
            }
        }
    }

    #pragma unroll
    for (int r = 0; r < TM; ++r) {
        const int m = m0 + trow * TM + r;
        if (m < M) {
            float rs = 1.f;
            if (EPI == 1) rs = rowscale[m];
            float* crow = C + (size_t)m * NT + tcol * TN;
            #pragma unroll
            for (int c = 0; c < TN; ++c) {
                const float b = bias[tcol * TN + c];
                crow[c] = acc[r][c] + ((EPI == 1) ? rs * b : b);
            }
        }
    }
}

// ---------------- edge kernel: h = relu(A[src]+B[dst]+attr*w1e); Hagg[dst] += h ----------------
__global__ void edge_kernel(const int* __restrict__ ei, const float* __restrict__ ea, int E) {
    const int e = blockIdx.x * 8 + (threadIdx.x >> 5);
    if (e >= E) return;
    const int lane = threadIdx.x & 31;
    const int src = ei[e];
    const int dst = ei[E + e];
    const float attr = ea[e];
    const float4* AB4 = reinterpret_cast<const float4*>(g_AB);
    const float4 a = AB4[(size_t)src * 64 + lane];        // A part (incl. b1)
    const float4 b = AB4[(size_t)dst * 64 + 32 + lane];   // B part
    const float4 w = reinterpret_cast<const float4*>(g_w1e)[lane];
    float4 h;
    h.x = fmaxf(fmaf(attr, w.x, a.x + b.x), 0.f);
    h.y = fmaxf(fmaf(attr, w.y, a.y + b.y), 0.f);
    h.z = fmaxf(fmaf(attr, w.z, a.z + b.z), 0.f);
    h.w = fmaxf(fmaf(attr, w.w, a.w + b.w), 0.f);
    atomicAdd(reinterpret_cast<float4*>(g_Hagg) + (size_t)dst * 32 + lane, h); // RED.128
    if (lane == 0) atomicAdd(&g_degf[dst], 1.f);
}

// ---------------- GRU gate fusion: out = (1-z)*n + z*x ----------------
__global__ void gates_kernel(const float* __restrict__ x, float* __restrict__ out, int M) {
    const int i = blockIdx.x * blockDim.x + threadIdx.x;  // over M*16 float4 groups
    if (i >= M * 16) return;
    const int n = i >> 4, q = i & 15;
    const float4* gi4 = reinterpret_cast<const float4*>(g_gi) + (size_t)n * 48 + q;
    const float4* gh4 = reinterpret_cast<const float4*>(g_gh) + (size_t)n * 48 + q;
    const float4 ir = gi4[0],  hr = gh4[0];
    const float4 iz = gi4[16], hz = gh4[16];
    const float4 inn = gi4[32], hn = gh4[32];
    const float4 xv = reinterpret_cast<const float4*>(x)[(size_t)n * 16 + q];
    float4 o;
#define GATE(comp)                                                   \
    {                                                                \
        const float rg = 1.f / (1.f + __expf(-(ir.comp + hr.comp))); \
        const float zg = 1.f / (1.f + __expf(-(iz.comp + hz.comp))); \
        const float nv = tanhf(fmaf(rg, hn.comp, inn.comp));         \
        o.comp = (1.f - zg) * nv + zg * xv.comp;                     \
    }
    GATE(x) GATE(y) GATE(z) GATE(w)
#undef GATE
    reinterpret_cast<float4*>(out)[(size_t)n * 16 + q] = o;
}

// ---------------- launch ----------------
extern "C" void kernel_launch(void* const* d_in, const int* in_sizes, int n_in,
                              void* d_out, int out_size) {
    const float* x   = (const float*)d_in[0];
    const int*   ei  = (const int*)d_in[1];
    const float* ea  = (const float*)d_in[2];
    const float* W1  = (const float*)d_in[3];
    const float* b1  = (const float*)d_in[4];
    const float* W2  = (const float*)d_in[5];
    const float* b2  = (const float*)d_in[6];
    const float* Wih = (const float*)d_in[7];
    const float* bih = (const float*)d_in[8];
    const float* Whh = (const float*)d_in[9];
    const float* bhh = (const float*)d_in[10];
    float* out = (float*)d_out;

    const int M = in_sizes[0] / NDIM;   // 100000
    const int E = in_sizes[2];          // 1600000

    void *pAB, *pHagg, *pdeg, *paggr, *pgi, *pgh;
    void *pWpre, *pb1e, *pW2t, *pWiht, *pWhht;
    cudaGetSymbolAddress(&pAB,   g_AB);
    cudaGetSymbolAddress(&pHagg, g_Hagg);
    cudaGetSymbolAddress(&pdeg,  g_degf);
    cudaGetSymbolAddress(&paggr, g_aggr);
    cudaGetSymbolAddress(&pgi,   g_gi);
    cudaGetSymbolAddress(&pgh,   g_gh);
    cudaGetSymbolAddress(&pWpre, g_Wpre);
    cudaGetSymbolAddress(&pb1e,  g_b1ext);
    cudaGetSymbolAddress(&pW2t,  g_W2t);
    cudaGetSymbolAddress(&pWiht, g_Wiht);
    cudaGetSymbolAddress(&pWhht, g_Whht);

    // opt-in to >48KB dynamic smem (idempotent; host-side only, capture-safe)
    cudaFuncSetAttribute(gemm_k<64, 256, 64, 8, 8, 0>,
                         cudaFuncAttributeMaxDynamicSharedMemorySize, 81920);
    cudaFuncSetAttribute(gemm_k<128, 64, 128, 8, 4, 1>,
                         cudaFuncAttributeMaxDynamicSharedMemorySize, 98304);
    cudaFuncSetAttribute(gemm_k<64, 192, 64, 8, 6, 0>,
                         cudaFuncAttributeMaxDynamicSharedMemorySize, 65536);

    prep_kernel<<<64, 256>>>(W1, b1, W2, Wih, Whh);
    zero_kernel<<<2048, 256>>>();

    // AB[N,256] = x @ Wpre + [b1|0]
    gemm_k<64, 256, 64, 8, 8, 0><<<(M + 63) / 64, 256, 81920>>>(
        x, (const float*)pWpre, (const float*)pb1e, nullptr, (float*)pAB, M);

    // per-edge relu + scatter-add into Hagg (+ degree count)
    edge_kernel<<<(E + 7) / 8, 256>>>(ei, ea, E);

    // aggr[N,64] = Hagg @ W2t + deg * b2
    gemm_k<128, 64, 128, 8, 4, 1><<<(M + 127) / 128, 256, 98304>>>(
        (const float*)pHagg, (const float*)pW2t, b2, (const float*)pdeg, (float*)paggr, M);

    // gi = aggr @ Wih^T + b_ih ; gh = x @ Whh^T + b_hh
    gemm_k<64, 192, 64, 8, 6, 0><<<(M + 63) / 64, 256, 65536>>>(
        (const float*)paggr, (const float*)pWiht, bih, nullptr, (float*)pgi, M);
    gemm_k<64, 192, 64, 8, 6, 0><<<(M + 63) / 64, 256, 65536>>>(
        x, (const float*)pWhht, bhh, nullptr, (float*)pgh, M);

    // GRU gates + output
    gates_kernel<<<(M * 16 + 255) / 256, 256>>>(x, out, M);
}

// round 3
// speedup vs baseline: 1.3857x; 1.3857x over previous
#include <cuda_runtime.h>
#include <math.h>

// Fixed dataset shapes
#define NN 100000
#define EMAX 1600000
#define NDIM 64

typedef unsigned long long ull;

// ---------------- scratch (__device__ globals) ----------------
__device__ float g_AB[NN * 256];      // per-node [A+b1 (128) | B (128)]
__device__ float g_Hagg[NN * 128];    // per-dst sum of relu(hidden)
__device__ float g_degf[NN];          // in-degree (float)
__device__ float g_aggr[NN * 64];     // aggregated messages after W2
// CSR build
__device__ int   g_cnt[NN];
__device__ int   g_off[NN + 1];
__device__ int   g_cur[NN];
__device__ int   g_esrc[EMAX];
__device__ float g_eattr[EMAX];
// repacked weights (k-pair interleaved for f32x2: [(k>>1)*NT + c]*2 + (k&1))
__device__ float g_Wpre[64 * 256];
__device__ float g_b1ext[256];
__device__ float g_w1e[128];
__device__ float g_W2t[128 * 64];
__device__ float g_Wiht[64 * 192];
__device__ float g_Whht[64 * 192];

// ---------------- f32x2 helpers ----------------
__device__ __forceinline__ void ffma2(ull& d, ull a, ull b) {
    asm("fma.rn.f32x2 %0, %1, %2, %0;" : "+l"(d) : "l"(a), "l"(b));
}
__device__ __forceinline__ float unpack_sum(ull v) {
    float lo, hi;
    asm("mov.b64 {%0, %1}, %2;" : "=f"(lo), "=f"(hi) : "l"(v));
    return lo + hi;
}

// ---------------- weight repack ----------------
__global__ void prep_kernel(const float* __restrict__ W1, const float* __restrict__ b1,
                            const float* __restrict__ W2,
                            const float* __restrict__ Wih, const float* __restrict__ Whh) {
    int t = blockIdx.x * blockDim.x + threadIdx.x;
    int stride = gridDim.x * blockDim.x;
    // Wpre: K=64, NT=256 (j<128 -> W1a^T, else W1b^T), k-pair interleaved
    for (int i = t; i < 64 * 256; i += stride) {
        int k = i >> 8, j = i & 255;
        float v = (j < 128) ? W1[j * 129 + k] : W1[(j - 128) * 129 + 64 + k];
        g_Wpre[((k >> 1) * 256 + j) * 2 + (k & 1)] = v;
    }
    for (int j = t; j < 256; j += stride) g_b1ext[j] = (j < 128) ? b1[j] : 0.f;
    for (int j = t; j < 128; j += stride) g_w1e[j] = W1[j * 129 + 128];
    // W2t: K=128, NT=64
    for (int i = t; i < 128 * 64; i += stride) {
        int k = i >> 6, j = i & 63;
        g_W2t[((k >> 1) * 64 + j) * 2 + (k & 1)] = W2[j * 128 + k];
    }
    // Wih^T / Whh^T: K=64, NT=192
    for (int i = t; i < 64 * 192; i += stride) {
        int k = i / 192, j = i % 192;
        g_Wiht[((k >> 1) * 192 + j) * 2 + (k & 1)] = Wih[j * 64 + k];
        g_Whht[((k >> 1) * 192 + j) * 2 + (k & 1)] = Whh[j * 64 + k];
    }
}

// ---------------- CSR build ----------------
__global__ void zero_cnt_kernel() {
    int t = blockIdx.x * blockDim.x + threadIdx.x;
    if (t < NN) g_cnt[t] = 0;
}

__global__ void hist_kernel(const int* __restrict__ ei, int E) {
    int e = blockIdx.x * blockDim.x + threadIdx.x;
    if (e < E) atomicAdd(&g_cnt[ei[E + e]], 1);
}

// single-block exclusive scan of g_cnt -> g_off (and g_cur), 4 elems/thread
__global__ void scan_kernel() {
    __shared__ int warpsums[32];
    __shared__ int s_carry;
    const int tid = threadIdx.x;
    const int lane = tid & 31, warp = tid >> 5;
    if (tid == 0) s_carry = 0;
    __syncthreads();
    for (int base = 0; base < NN; base += 4096) {
        int idx = base + tid * 4;
        int v0 = 0, v1 = 0, v2 = 0, v3 = 0;
        if (idx + 3 < NN) {
            int4 v = *reinterpret_cast<const int4*>(&g_cnt[idx]);
            v0 = v.x; v1 = v.y; v2 = v.z; v3 = v.w;
        } else {
            if (idx + 0 < NN) v0 = g_cnt[idx + 0];
            if (idx + 1 < NN) v1 = g_cnt[idx + 1];
            if (idx + 2 < NN) v2 = g_cnt[idx + 2];
            if (idx + 3 < NN) v3 = g_cnt[idx + 3];
        }
        int s0 = v0, s1 = s0 + v1, s2 = s1 + v2, s3 = s2 + v3;
        int incl = s3;
        #pragma unroll
        for (int o = 1; o < 32; o <<= 1) {
            int tt = __shfl_up_sync(0xffffffffu, incl, o);
            if (lane >= o) incl += tt;
        }
        if (lane == 31) warpsums[warp] = incl;
        __syncthreads();
        if (warp == 0) {
            int ws = warpsums[lane];
            #pragma unroll
            for (int o = 1; o < 32; o <<= 1) {
                int tt = __shfl_up_sync(0xffffffffu, ws, o);
                if (lane >= o) ws += tt;
            }
            warpsums[lane] = ws;
        }
        __syncthreads();
        int warpbase = (warp == 0) ? 0 : warpsums[warp - 1];
        int texcl = incl - s3 + warpbase + s_carry;
        int o0 = texcl, o1 = texcl + s0, o2 = texcl + s1, o3 = texcl + s2;
        if (idx + 3 < NN) {
            *reinterpret_cast<int4*>(&g_off[idx]) = make_int4(o0, o1, o2, o3);
            *reinterpret_cast<int4*>(&g_cur[idx]) = make_int4(o0, o1, o2, o3);
        } else {
            if (idx + 0 < NN) { g_off[idx + 0] = o0; g_cur[idx + 0] = o0; }
            if (idx + 1 < NN) { g_off[idx + 1] = o1; g_cur[idx + 1] = o1; }
            if (idx + 2 < NN) { g_off[idx + 2] = o2; g_cur[idx + 2] = o2; }
            if (idx + 3 < NN) { g_off[idx + 3] = o3; g_cur[idx + 3] = o3; }
        }
        __syncthreads();
        if (tid == 0) s_carry += warpsums[31];
        __syncthreads();
    }
    if (tid == 0) g_off[NN] = s_carry;
}

__global__ void scatter_kernel(const int* __restrict__ ei, const float* __restrict__ ea, int E) {
    int e = blockIdx.x * blockDim.x + threadIdx.x;
    if (e >= E) return;
    int dst = ei[E + e];
    int p = atomicAdd(&g_cur[dst], 1);
    g_esrc[p] = ei[e];
    g_eattr[p] = ea[e];
}

// ---------------- aggregation: one warp per dst, no atomics ----------------
__global__ void agg_kernel() {
    const int dst = blockIdx.x * 8 + (threadIdx.x >> 5);
    if (dst >= NN) return;
    const int lane = threadIdx.x & 31;
    const int start = g_off[dst], end = g_off[dst + 1];
    const float4* AB4 = reinterpret_cast<const float4*>(g_AB);
    const float4 b = AB4[(size_t)dst * 64 + 32 + lane];
    const float4 w = reinterpret_cast<const float4*>(g_w1e)[lane];
    float4 acc = make_float4(0.f, 0.f, 0.f, 0.f);
    int e = start;
    for (; e + 1 < end; e += 2) {
        const int s0 = g_esrc[e], s1 = g_esrc[e + 1];
        const float t0 = g_eattr[e], t1 = g_eattr[e + 1];
        const float4 a0 = AB4[(size_t)s0 * 64 + lane];
        const float4 a1 = AB4[(size_t)s1 * 64 + lane];
        acc.x += fmaxf(fmaf(t0, w.x, a0.x + b.x), 0.f) + fmaxf(fmaf(t1, w.x, a1.x + b.x), 0.f);
        acc.y += fmaxf(fmaf(t0, w.y, a0.y + b.y), 0.f) + fmaxf(fmaf(t1, w.y, a1.y + b.y), 0.f);
        acc.z += fmaxf(fmaf(t0, w.z, a0.z + b.z), 0.f) + fmaxf(fmaf(t1, w.z, a1.z + b.z), 0.f);
        acc.w += fmaxf(fmaf(t0, w.w, a0.w + b.w), 0.f) + fmaxf(fmaf(t1, w.w, a1.w + b.w), 0.f);
    }
    if (e < end) {
        const int s0 = g_esrc[e];
        const float t0 = g_eattr[e];
        const float4 a0 = AB4[(size_t)s0 * 64 + lane];
        acc.x += fmaxf(fmaf(t0, w.x, a0.x + b.x), 0.f);
        acc.y += fmaxf(fmaf(t0, w.y, a0.y + b.y), 0.f);
        acc.z += fmaxf(fmaf(t0, w.z, a0.z + b.z), 0.f);
        acc.w += fmaxf(fmaf(t0, w.w, a0.w + b.w), 0.f);
    }
    reinterpret_cast<float4*>(g_Hagg)[(size_t)dst * 32 + lane] = acc;
    if (lane == 0) g_degf[dst] = (float)(end - start);
}

// ---------------- f32x2 GEMM: C[M,NT] = A[M,KK] @ W + bias (EPI1: rowscale*bias) ----------------
// Thread tid: tcol = tid%TCOLS, trow = tid/TCOLS; cols handled = tcol + c*TCOLS.
// W in gmem is k-pair interleaved; acc.lo/hi hold even/odd-k partials.
template <int MT, int NT, int KK, int TM, int TN, int EPI>
__launch_bounds__(256, 2)
__global__ void gemm_k(const float* __restrict__ A, const float* __restrict__ W,
                       const float* __restrict__ bias, const float* __restrict__ rowscale,
                       float* __restrict__ C, int M) {
    constexpr int TCOLS = NT / TN;
    constexpr int TROWS = MT / TM;
    static_assert(TCOLS * TROWS == 256, "bad tiling");
    extern __shared__ float smem[];
    float* As = smem;            // MT x KK
    float* Ws = smem + MT * KK;  // KK x NT (pair-interleaved)

    const int tid = threadIdx.x;
    const int m0 = blockIdx.x * MT;
    {
        const float4* Ag = reinterpret_cast<const float4*>(A) + (size_t)m0 * (KK / 4);
        float4* As4 = reinterpret_cast<float4*>(As);
        int rows = M - m0; if (rows > MT) rows = MT;
        const int lim = rows * (KK / 4);
        #pragma unroll 4
        for (int i = tid; i < MT * KK / 4; i += 256)
            As4[i] = (i < lim) ? Ag[i] : make_float4(0.f, 0.f, 0.f, 0.f);
        const float4* Wg = reinterpret_cast<const float4*>(W);
        float4* Ws4 = reinterpret_cast<float4*>(Ws);
        #pragma unroll 4
        for (int i = tid; i < KK * NT / 4; i += 256) Ws4[i] = Wg[i];
    }
    __syncthreads();

    const int tcol = tid % TCOLS;
    const int trow = tid / TCOLS;
    ull acc[TM][TN];
    #pragma unroll
    for (int r = 0; r < TM; ++r)
        #pragma unroll
        for (int c = 0; c < TN; ++c) acc[r][c] = 0ull;

    const ull* As2 = reinterpret_cast<const ull*>(As) + (trow * TM) * (KK / 2);
    const ull* Ws2 = reinterpret_cast<const ull*>(Ws) + tcol;

    #pragma unroll 4
    for (int k2 = 0; k2 < KK / 2; ++k2) {
        ull a2[TM], w2[TN];
        #pragma unroll
        for (int r = 0; r < TM; ++r) a2[r] = As2[r * (KK / 2) + k2];
        #pragma unroll
        for (int c = 0; c < TN; ++c) w2[c] = Ws2[k2 * NT + c * TCOLS];
        #pragma unroll
        for (int r = 0; r < TM; ++r)
            #pragma unroll
            for (int c = 0; c < TN; ++c) ffma2(acc[r][c], a2[r], w2[c]);
    }

    #pragma unroll
    for (int r = 0; r < TM; ++r) {
        const int m = m0 + trow * TM + r;
        if (m < M) {
            float rs = 1.f;
            if (EPI == 1) rs = rowscale[m];
            float* crow = C + (size_t)m * NT;
            #pragma unroll
            for (int c = 0; c < TN; ++c) {
                const int j = tcol + c * TCOLS;
                const float b = bias[j];
                crow[j] = unpack_sum(acc[r][c]) + ((EPI == 1) ? rs * b : b);
            }
        }
    }
}

// ---------------- fused GRU: dual f32x2 GEMM (aggr@Wih^T, x@Whh^T) + gates epilogue ----------------
// MT=16, NT=192, KK=64, TM=4, TN=3, TCOLS=64, TROWS=4.
// Thread's 3 columns are exactly (i_r, i_z, i_n) at offset tcol.
__launch_bounds__(256, 2)
__global__ void gru_kernel(const float* __restrict__ Aggr, const float* __restrict__ X,
                           const float* __restrict__ bih, const float* __restrict__ bhh,
                           float* __restrict__ out, int M) {
    constexpr int MT = 16, KK = 64, NT = 192, TM = 4, TCOLS = 64;
    extern __shared__ float smem[];
    float* As = smem;                 // 16x64 (aggr)
    float* Xs = smem + MT * KK;       // 16x64 (x)
    float* Wi = smem + 2 * MT * KK;   // 64x192 interleaved
    float* Wh = Wi + KK * NT;

    const int tid = threadIdx.x;
    const int m0 = blockIdx.x * MT;
    {
        int rows = M - m0; if (rows > MT) rows = MT;
        const int lim = rows * (KK / 4);
        const float4* Ag = reinterpret_cast<const float4*>(Aggr) + (size_t)m0 * (KK / 4);
        const float4* Xg = reinterpret_cast<const float4*>(X) + (size_t)m0 * (KK / 4);
        float4* As4 = reinterpret_cast<float4*>(As);
        float4* Xs4 = reinterpret_cast<float4*>(Xs);
        for (int i = tid; i < MT * KK / 4; i += 256) {
            As4[i] = (i < lim) ? Ag[i] : make_float4(0.f, 0.f, 0.f, 0.f);
            Xs4[i] = (i < lim) ? Xg[i] : make_float4(0.f, 0.f, 0.f, 0.f);
        }
        const float4* Wig = reinterpret_cast<const float4*>(g_Wiht);
        const float4* Whg = reinterpret_cast<const float4*>(g_Whht);
        float4* Wi4 = reinterpret_cast<float4*>(Wi);
        float4* Wh4 = reinterpret_cast<float4*>(Wh);
        #pragma unroll 4
        for (int i = tid; i < KK * NT / 4; i += 256) { Wi4[i] = Wig[i]; Wh4[i] = Whg[i]; }
    }
    __syncthreads();

    const int tcol = tid % TCOLS;
    const int trow = tid / TCOLS;
    ull gi[TM][3], gh[TM][3];
    #pragma unroll
    for (int r = 0; r < TM; ++r)
        #pragma unroll
        for (int c = 0; c < 3; ++c) { gi[r][c] = 0ull; gh[r][c] = 0ull; }

    const ull* As2 = reinterpret_cast<const ull*>(As) + (trow * TM) * (KK / 2);
    const ull* Xs2 = reinterpret_cast<const ull*>(Xs) + (trow * TM) * (KK / 2);
    const ull* Wi2 = reinterpret_cast<const ull*>(Wi) + tcol;
    const ull* Wh2 = reinterpret_cast<const ull*>(Wh) + tcol;

    #pragma unroll 4
    for (int k2 = 0; k2 < KK / 2; ++k2) {
        ull a2[TM], x2[TM], wi2[3], wh2[3];
        #pragma unroll
        for (int r = 0; r < TM; ++r) {
            a2[r] = As2[r * (KK / 2) + k2];
            x2[r] = Xs2[r * (KK / 2) + k2];
        }
        #pragma unroll
        for (int c = 0; c < 3; ++c) {
            wi2[c] = Wi2[k2 * NT + c * TCOLS];
            wh2[c] = Wh2[k2 * NT + c * TCOLS];
        }
        #pragma unroll
        for (int r = 0; r < TM; ++r)
            #pragma unroll
            for (int c = 0; c < 3; ++c) {
                ffma2(gi[r][c], a2[r], wi2[c]);
                ffma2(gh[r][c], x2[r], wh2[c]);
            }
    }

    const float bir = bih[tcol],      bhr = bhh[tcol];
    const float biz = bih[tcol + 64], bhz = bhh[tcol + 64];
    const float bin = bih[tcol + 128], bhn = bhh[tcol + 128];
    #pragma unroll
    for (int r = 0; r < TM; ++r) {
        const int m = m0 + trow * TM + r;
        if (m < M) {
            const float ir = unpack_sum(gi[r][0]) + bir;
            const float hr = unpack_sum(gh[r][0]) + bhr;
            const float iz = unpack_sum(gi[r][1]) + biz;
            const float hz = unpack_sum(gh[r][1]) + bhz;
            const float in_ = unpack_sum(gi[r][2]) + bin;
            const float hn = unpack_sum(gh[r][2]) + bhn;
            const float rg = 1.f / (1.f + __expf(-(ir + hr)));
            const float zg = 1.f / (1.f + __expf(-(iz + hz)));
            const float nv = tanhf(fmaf(rg, hn, in_));
            const float xv = Xs[(trow * TM + r) * KK + tcol];
            out[(size_t)m * 64 + tcol] = (1.f - zg) * nv + zg * xv;
        }
    }
}

// ---------------- launch ----------------
extern "C" void kernel_launch(void* const* d_in, const int* in_sizes, int n_in,
                              void* d_out, int out_size) {
    const float* x   = (const float*)d_in[0];
    const int*   ei  = (const int*)d_in[1];
    const float* ea  = (const float*)d_in[2];
    const float* W1  = (const float*)d_in[3];
    const float* b1  = (const float*)d_in[4];
    const float* W2  = (const float*)d_in[5];
    const float* b2  = (const float*)d_in[6];
    const float* Wih = (const float*)d_in[7];
    const float* bih = (const float*)d_in[8];
    const float* Whh = (const float*)d_in[9];
    const float* bhh = (const float*)d_in[10];
    float* out = (float*)d_out;

    const int M = in_sizes[0] / NDIM;  // 100000
    const int E = in_sizes[1] / 2;     // 1600000

    void *pAB, *pHagg, *pdeg, *paggr, *pWpre, *pb1e, *pW2t;
    cudaGetSymbolAddress(&pAB,   g_AB);
    cudaGetSymbolAddress(&pHagg, g_Hagg);
    cudaGetSymbolAddress(&pdeg,  g_degf);
    cudaGetSymbolAddress(&paggr, g_aggr);
    cudaGetSymbolAddress(&pWpre, g_Wpre);
    cudaGetSymbolAddress(&pb1e,  g_b1ext);
    cudaGetSymbolAddress(&pW2t,  g_W2t);

    constexpr int SM1 = (32 * 64 + 64 * 256) * 4;   // 73728
    constexpr int SM2 = (64 * 128 + 128 * 64) * 4;  // 65536
    constexpr int SMG = (2 * 16 * 64 + 2 * 64 * 192) * 4;  // 106496
    cudaFuncSetAttribute(gemm_k<32, 256, 64, 8, 4, 0>,
                         cudaFuncAttributeMaxDynamicSharedMemorySize, SM1);
    cudaFuncSetAttribute(gemm_k<64, 64, 128, 8, 2, 1>,
                         cudaFuncAttributeMaxDynamicSharedMemorySize, SM2);
    cudaFuncSetAttribute(gru_kernel,
                         cudaFuncAttributeMaxDynamicSharedMemorySize, SMG);

    prep_kernel<<<64, 256>>>(W1, b1, W2, Wih, Whh);
    zero_cnt_kernel<<<(NN + 255) / 256, 256>>>();
    hist_kernel<<<(E + 255) / 256, 256>>>(ei, E);

    // AB[N,256] = x @ Wpre + [b1|0]
    gemm_k<32, 256, 64, 8, 4, 0><<<(M + 31) / 32, 256, SM1>>>(
        x, (const float*)pWpre, (const float*)pb1e, nullptr, (float*)pAB, M);

    scan_kernel<<<1, 1024>>>();
    scatter_kernel<<<(E + 255) / 256, 256>>>(ei, ea, E);

    // per-dst aggregation (no atomics)
    agg_kernel<<<(NN + 7) / 8, 256>>>();

    // aggr[N,64] = Hagg @ W2t + deg * b2
    gemm_k<64, 64, 128, 8, 2, 1><<<(M + 63) / 64, 256, SM2>>>(
        (const float*)pHagg, (const float*)pW2t, b2, (const float*)pdeg, (float*)paggr, M);

    // fused: gi = aggr@Wih^T+bih, gh = x@Whh^T+bhh, GRU gates, write out
    gru_kernel<<<(M + 15) / 16, 256, SMG>>>(
        (const float*)paggr, x, bih, bhh, out, M);
}